// round 11
// baseline (speedup 1.0000x reference)
#include <cuda_runtime.h>
#include <cuda_bf16.h>
#include <cstdint>

// ContinuousEmbedding: out[b,f,:] = sum_k weight[k,:] / (|idx(x[b,f]) - k| + 1)
// = 64x64 table T (16 KB) indexed by bucket.
//
// R11: per-warp TMA bulk stores. All STG variants converged at ~23us because
// the warp-side store issue bill (262k STG.128 x 12cyc) is the floor. Replace
// with: each warp fills a 4KB (16-row) smem staging tile via STS.128 (3x
// cheaper issue), lane 0 fires cp.async.bulk shared->global (per-thread bulk
// group: NO block sync, unlike failed R4), double-buffered. 148 persistent
// blocks x 512 thr (1/SM, 128KB staging). Table built by 2 builder blocks +
// acquire-spin (R10 protocol), gathered via __ldg (L1-resident 16KB).

#define NUM_BINS 63
#define KDIM 64          // NUM_BINS + 1
#define EMB_DIM 64
#define ROWS_TILE 16
#define TILE_F4   (ROWS_TILE * EMB_DIM / 4)     // 256 float4 = 4 KB
#define TILE_BYTES (TILE_F4 * 16)
#define WARPS_BLK 16
#define NBUILD 2         // 2 blocks x 512 thr = 1024 float4 table entries

__device__ float g_table[KDIM * EMB_DIM];   // 1024 float4
__device__ int   g_ready;
__device__ int   g_done;

__device__ __forceinline__ uint32_t smem_u32(const void* p) {
    return (uint32_t)__cvta_generic_to_shared(p);
}

extern __shared__ float4 smem_stage[];      // [WARPS_BLK][2][TILE_F4] = 128 KB

__global__ void __launch_bounds__(512, 1)
embed_tma(const float* __restrict__ x,
          const float* __restrict__ low,     // [64]; low[0]=-inf, bins=low[1..]
          const float* __restrict__ weight,  // [64*64]
          float* __restrict__ out,
          int n_rows)
{
    const int tid = threadIdx.x;
    const int bid = blockIdx.x;

    // ---- builders: blocks 0..1 compute 512 table entries each -------------
    if (bid < NBUILD) {
        __shared__ float srecip[KDIM];
        if (tid < KDIM) srecip[tid] = 1.0f / (float)(tid + 1);
        __syncthreads();
        const int e = bid * 512 + tid;         // float4 entry 0..1023
        const int r = e >> 4;
        const int c = e & 15;
        const float4* w4 = reinterpret_cast<const float4*>(weight);
        float4 acc = make_float4(0.f, 0.f, 0.f, 0.f);
#pragma unroll 16
        for (int k = 0; k < KDIM; ++k) {
            int d = r - k; if (d < 0) d = -d;
            const float  s = srecip[d];
            const float4 w = __ldg(w4 + k * 16 + c);
            acc.x = fmaf(w.x, s, acc.x);
            acc.y = fmaf(w.y, s, acc.y);
            acc.z = fmaf(w.z, s, acc.z);
            acc.w = fmaf(w.w, s, acc.w);
        }
        reinterpret_cast<float4*>(g_table)[e] = acc;
        __threadfence();
        __syncthreads();
        if (tid == 0) atomicAdd(&g_ready, 1);
    }

    // ---- all blocks: wait for the table ------------------------------------
    if (tid == 0) {
        int r;
        do {
            asm volatile("ld.global.acquire.gpu.b32 %0, [%1];"
                         : "=r"(r) : "l"(&g_ready) : "memory");
        } while (r < NBUILD);
    }
    __syncthreads();

    // ---- per-warp TMA-store pipeline ---------------------------------------
    const int lane = tid & 31;
    const int warp = tid >> 5;
    float4* stage = smem_stage + warp * (2 * TILE_F4);
    const float4* table = reinterpret_cast<const float4*>(g_table);

    const int gw = bid * WARPS_BLK + warp;
    const int nw = gridDim.x * WARPS_BLK;
    const int n_tiles = n_rows / ROWS_TILE;

    int it = 0;
    for (int tile = gw; tile < n_tiles; tile += nw, ++it) {
        const int base = tile * ROWS_TILE;

        // bucket index for row base+lane (lanes 0..15): g = #{j: bins[j] < x}
        // arithmetic guess (bins ~ linspace(-3.1,3.1,63)) + EXACT fixup
        int g = 0;
        if (lane < ROWS_TILE) {
            const float xv = __ldg(x + base + lane);
            g = (int)floorf((xv + 3.1f) * 10.0f) + 1;
            g = max(0, min(NUM_BINS, g));
            while (g > 0 && !(xv > __ldg(low + g))) --g;
            while (g < NUM_BINS && (xv > __ldg(low + g + 1))) ++g;
        }

        // buffer free? (<=1 bulk group pending for this thread's warp)
        const int buf = it & 1;
        if (lane == 0)
            asm volatile("cp.async.bulk.wait_group.read 1;" ::: "memory");
        __syncwarp();

        // fill 256 float4: lane L writes slots L, L+32, ..., L+224
        float4* sb = stage + buf * TILE_F4;
#pragma unroll
        for (int t = 0; t < 8; ++t) {
            const int s    = lane + 32 * t;
            const int ridx = s >> 4;           // row within tile 0..15
            const int prt  = s & 15;           // float4 slot within row
            const int idx  = __shfl_sync(0xffffffffu, g, ridx);
            sb[s] = __ldg(&table[(idx << 4) + prt]);
        }
        __syncwarp();                          // STS visible to lane 0

        if (lane == 0) {
            asm volatile("fence.proxy.async.shared::cta;" ::: "memory");
            const float* gd = out + (size_t)base * EMB_DIM;
            asm volatile(
                "cp.async.bulk.global.shared::cta.bulk_group [%0], [%1], %2;"
                :: "l"(gd), "r"(smem_u32(sb)), "r"((uint32_t)TILE_BYTES)
                : "memory");
            asm volatile("cp.async.bulk.commit_group;" ::: "memory");
        }
    }
    // drain: smem must stay live until TMA reads complete
    if (lane == 0)
        asm volatile("cp.async.bulk.wait_group 0;" ::: "memory");
    __syncwarp();

    // ---- remainder rows (n_rows % 16), block 0 warp 0 ---------------------
    const int rem_base = n_tiles * ROWS_TILE;
    if (bid == 0 && warp == 0 && rem_base < n_rows) {
        for (int r = rem_base; r < n_rows; ++r) {
            int gg = 0;
            if (lane == 0) {
                const float xv = __ldg(x + r);
                gg = (int)floorf((xv + 3.1f) * 10.0f) + 1;
                gg = max(0, min(NUM_BINS, gg));
                while (gg > 0 && !(xv > __ldg(low + gg))) --gg;
                while (gg < NUM_BINS && (xv > __ldg(low + gg + 1))) ++gg;
            }
            gg = __shfl_sync(0xffffffffu, gg, 0);
            if (lane < 16)
                reinterpret_cast<float4*>(out)[(size_t)r * 16 + lane] =
                    table[(gg << 4) + lane];
        }
    }

    // ---- self-reset so every launch is identical ---------------------------
    __syncthreads();
    if (tid == 0) {
        const int prev = atomicAdd(&g_done, 1);
        if (prev == (int)gridDim.x - 1) {
            atomicExch(&g_done, 0);
            atomicExch(&g_ready, 0);
        }
    }
}

extern "C" void kernel_launch(void* const* d_in, const int* in_sizes, int n_in,
                              void* d_out, int out_size) {
    const float* x      = (const float*)d_in[0];   // [B*F]
    const float* low    = (const float*)d_in[1];   // [64]
    // d_in[2] = high [64] (redundant with low for the bucket computation)
    const float* weight = (const float*)d_in[3];   // [64*64]

    float* out = (float*)d_out;
    const int n_rows = out_size / EMB_DIM;         // 524288

    const int smem_bytes = WARPS_BLK * 2 * TILE_BYTES;   // 128 KB
    static int attr_done = 0;
    if (!attr_done) {
        cudaFuncSetAttribute(embed_tma,
                             cudaFuncAttributeMaxDynamicSharedMemorySize,
                             smem_bytes);
        attr_done = 1;
    }

    // 148 persistent blocks (1/SM at 128 KB smem); always >= NBUILD.
    int blocks = 148;
    const int n_tiles = n_rows / ROWS_TILE;
    int need = (n_tiles + WARPS_BLK - 1) / WARPS_BLK;
    if (blocks > need) blocks = need;
    if (blocks < NBUILD) blocks = NBUILD;

    embed_tma<<<blocks, 512, smem_bytes>>>(x, low, weight, out, n_rows);
}

// round 12
// speedup vs baseline: 1.5875x; 1.5875x over previous
#include <cuda_runtime.h>
#include <cuda_bf16.h>
#include <cstdint>

// ContinuousEmbedding: out[b,f,:] = sum_k weight[k,:] / (|idx(x[b,f]) - k| + 1)
// = 64x64 table T (16 KB = 1024 float4) indexed by bucket.
//
// R12 = R10 (single kernel, builder blocks + flag) with the spin fixed:
// __nanosleep backoff so ~2048 pollers stop hammering the g_ready L2 line
// (R10's profiled dur was ~4us over the R9 fan-out; suspect spin contention).
// Fan-out unchanged: measured-floor shape, 8-deep batched
// {shfl -> LDG.128 table -> STG.128.cs}, launch_bounds(256,5).

#define NUM_BINS 63
#define KDIM 64          // NUM_BINS + 1
#define EMB_DIM 64
#define NBUILD 8         // builder blocks: 8 x 128 float4 entries

__device__ float g_table[KDIM * EMB_DIM];   // 4096 floats = 1024 float4
__device__ int   g_ready;                   // builders done (0..NBUILD)
__device__ int   g_done;                    // blocks finished (for reset)

__global__ void __launch_bounds__(256, 5)
embed_fused(const float* __restrict__ x,
            const float* __restrict__ low,     // [64]; low[0]=-inf, bins=low[1..]
            const float* __restrict__ weight,  // [64*64]
            float4* __restrict__ out,
            int n_rows)
{
    const int tid = threadIdx.x;
    const int bid = blockIdx.x;

    // ---- phase 1a: builder blocks compute 128 table entries each ----------
    if (bid < NBUILD) {
        __shared__ float srecip[KDIM];
        if (tid < KDIM) srecip[tid] = 1.0f / (float)(tid + 1);
        __syncthreads();
        if (tid < 128) {
            const int e = bid * 128 + tid;     // float4 entry 0..1023
            const int r = e >> 4;              // 0..63
            const int c = e & 15;              // 0..15
            const float4* w4 = reinterpret_cast<const float4*>(weight);
            float4 acc = make_float4(0.f, 0.f, 0.f, 0.f);
#pragma unroll 16
            for (int k = 0; k < KDIM; ++k) {
                int d = r - k; if (d < 0) d = -d;
                const float  s = srecip[d];
                const float4 w = __ldg(w4 + k * 16 + c);
                acc.x = fmaf(w.x, s, acc.x);
                acc.y = fmaf(w.y, s, acc.y);
                acc.z = fmaf(w.z, s, acc.z);
                acc.w = fmaf(w.w, s, acc.w);
            }
            reinterpret_cast<float4*>(g_table)[e] = acc;
        }
        __threadfence();                       // table writes visible (gpu scope)
        __syncthreads();
        if (tid == 0) atomicAdd(&g_ready, 1);
    }

    // ---- phase 1b (all blocks): bucket index, overlapped with build -------
    const int lane = tid & 31;
    const int warp = tid >> 5;
    const int half = lane >> 4;        // row-within-pair
    const int part = lane & 15;        // float4 slot within a 64-float row
    const int base = (bid * 8 + warp) * 32;
    const bool active = (base < n_rows);

    // g = #{ j : bins[j] < x }: arithmetic guess (bins ~ linspace(-3.1,3.1))
    // then EXACT fixup against the real bin values (low[g] == bins[g-1]).
    int g = 0;
    if (active && base + lane < n_rows) {
        const float xv = __ldg(x + base + lane);
        g = (int)floorf((xv + 3.1f) * 10.0f) + 1;
        g = max(0, min(NUM_BINS, g));
        while (g > 0 && !(xv > __ldg(low + g))) --g;
        while (g < NUM_BINS && (xv > __ldg(low + g + 1))) ++g;
    }

    // ---- phase 2: wait for the table (backoff spin, low L2 pressure) ------
    if (tid == 0) {
        int r;
        asm volatile("ld.global.acquire.gpu.b32 %0, [%1];"
                     : "=r"(r) : "l"(&g_ready) : "memory");
        while (r < NBUILD) {
            __nanosleep(256);
            asm volatile("ld.global.acquire.gpu.b32 %0, [%1];"
                         : "=r"(r) : "l"(&g_ready) : "memory");
        }
    }
    __syncthreads();

    // ---- phase 3: fan-out (measured-floor shape) ---------------------------
    if (active) {
        const float4* table = reinterpret_cast<const float4*>(g_table);
        const bool full = (base + 32 <= n_rows);   // uniform within warp
#pragma unroll
        for (int h = 0; h < 2; ++h) {
            int    idxs[8];
            float4 v[8];
#pragma unroll
            for (int j = 0; j < 8; ++j)
                idxs[j] = __shfl_sync(0xffffffffu, g, (h * 8 + j) * 2 + half);
#pragma unroll
            for (int j = 0; j < 8; ++j)
                v[j] = __ldg(&table[(idxs[j] << 4) + part]);
            if (full) {
#pragma unroll
                for (int j = 0; j < 8; ++j)
                    __stcs(&out[(size_t)(base + (h * 8 + j) * 2) * 16 + lane], v[j]);
            } else {
#pragma unroll
                for (int j = 0; j < 8; ++j) {
                    const int r = base + (h * 8 + j) * 2 + half;
                    if (r < n_rows)
                        __stcs(&out[(size_t)r * 16 + part], v[j]);
                }
            }
        }
    }

    // ---- phase 4: self-reset so every launch is identical ------------------
    __syncthreads();
    if (tid == 0) {
        const int prev = atomicAdd(&g_done, 1);
        if (prev == (int)gridDim.x - 1) {      // last block: reset protocol
            atomicExch(&g_done, 0);
            atomicExch(&g_ready, 0);
        }
    }
}

extern "C" void kernel_launch(void* const* d_in, const int* in_sizes, int n_in,
                              void* d_out, int out_size) {
    const float* x      = (const float*)d_in[0];   // [B*F]
    const float* low    = (const float*)d_in[1];   // [64]
    // d_in[2] = high [64] (redundant with low for the bucket computation)
    const float* weight = (const float*)d_in[3];   // [64*64]

    float4* out = (float4*)d_out;
    const int n_rows = out_size / EMB_DIM;         // 524288

    // One-shot grid: 8 warps x 32 rows per block. At least NBUILD blocks.
    int blocks = (n_rows + 255) / 256;             // 2048 for the real shape
    if (blocks < NBUILD) blocks = NBUILD;

    embed_fused<<<blocks, 256>>>(x, low, weight, out, n_rows);
}